// round 17
// baseline (speedup 1.0000x reference)
#include <cuda_runtime.h>
#include <cuda_fp16.h>
#include <cstdint>

// Problem constants
#define M_TOT 25216          // 128 * 197
#define C_DIM 768
#define N3    2304           // 3 * C
#define NTOK  197
#define NHEAD 12
#define HD    64
#define NT2   208            // padded smem rows for Q/K/V (max ldsm row = 207)
#define LOG2E 1.44269504f
#define NBH   (NHEAD * 128)  // 1536 (b,h) pairs
#define APERS 296            // persistent attention CTAs (2 per SM)

// Scratch (device globals: allocation-free)
__device__ __half g_q  [(size_t)M_TOT * C_DIM];   // fp16 head-major, scaled 0.125*log2e
__device__ __half g_k  [(size_t)M_TOT * C_DIM];
__device__ __half g_v  [(size_t)M_TOT * C_DIM];
__device__ __half g_att[(size_t)M_TOT * C_DIM];   // attention output (fp16)
__device__ __half g_xh [(size_t)M_TOT * C_DIM];
__device__ __half g_wqkv[(size_t)N3 * C_DIM];
__device__ __half g_wproj[(size_t)C_DIM * C_DIM];

// Fragment-layout bias (scaled by log2e): [h][blk(13)][jt(26)][lane(32)] -> uint2
#define BIAS2_ELEMS (NHEAD * 13 * 26 * 32)
__device__ uint2 g_bias2[BIAS2_ELEMS];

#define CVT_N1 (M_TOT * C_DIM)
#define CVT_N2 (N3 * C_DIM)
#define CVT_N3 (C_DIM * C_DIM)
#define CVT_TOT4 ((CVT_N1 + CVT_N2 + CVT_N3) / 4)
#define CVT_BLOCKS ((CVT_TOT4 + 255) / 256)
#define BIAS_BLOCKS ((BIAS2_ELEMS + 255) / 256)

__device__ __forceinline__ float fast_exp2(float x) {
    float y; asm("ex2.approx.f32 %0, %1;" : "=f"(y) : "f"(x)); return y;
}

__device__ __forceinline__ float bias_val(
    const int* relIdx, const float* table, int i, int j, int h)
{
    if (j >= NTOK) return -60000.f;      // exp2 -> 0 exactly
    if (i >= NTOK) return 0.f;
    return table[relIdx[i * NTOK + j] * NHEAD + h] * LOG2E;   // base-2 domain
}

// Fused prep: blocks [0,CVT_BLOCKS) convert x/qkv_w/proj_w; the rest build bias frags.
__global__ __launch_bounds__(256) void prep_kernel(
    const float* __restrict__ inA, __half* __restrict__ outA,
    const float* __restrict__ inB, __half* __restrict__ outB,
    const float* __restrict__ inC, __half* __restrict__ outC,
    const int* __restrict__ relIdx, const float* __restrict__ table,
    uint2* __restrict__ biasF2)
{
    if (blockIdx.x < CVT_BLOCKS) {
        int q4 = blockIdx.x * 256 + threadIdx.x;
        if (q4 >= CVT_TOT4) return;
        int i = q4 * 4;
        const float* in; __half* out;
        if (i < CVT_N1)               { in = inA + i;                  out = outA + i; }
        else if (i < CVT_N1 + CVT_N2) { in = inB + (i - CVT_N1);       out = outB + (i - CVT_N1); }
        else                          { in = inC + (i - CVT_N1 - CVT_N2); out = outC + (i - CVT_N1 - CVT_N2); }
        float4 v = *(const float4*)in;
        __half2 a = __floats2half2_rn(v.x, v.y);
        __half2 b = __floats2half2_rn(v.z, v.w);
        uint2 u; u.x = *(uint32_t*)&a; u.y = *(uint32_t*)&b;
        *(uint2*)out = u;
    } else {
        int idx = (blockIdx.x - CVT_BLOCKS) * 256 + threadIdx.x;
        if (idx >= BIAS2_ELEMS) return;
        int lane = idx & 31;
        int t = idx >> 5;
        int jt = t % 26; t /= 26;
        int blk = t % 13;
        int h = t / 13;
        int g = lane >> 2, c = lane & 3;
        int i = blk * 16 + g;
        int j = jt * 8 + 2 * c;
        __half2 lo = __floats2half2_rn(bias_val(relIdx, table, i, j, h),
                                       bias_val(relIdx, table, i, j + 1, h));
        __half2 hi = __floats2half2_rn(bias_val(relIdx, table, i + 8, j, h),
                                       bias_val(relIdx, table, i + 8, j + 1, h));
        uint2 u; u.x = *(uint32_t*)&lo; u.y = *(uint32_t*)&hi;
        biasF2[idx] = u;
    }
}

// ---------------------------------------------------------------------------
// fp16 tensor-core GEMM (unchanged from round 16 — passing).
// ---------------------------------------------------------------------------
#define GBK 64
#define TILE_BYTES (128 * 128)
#define GSTAGE_BYTES (2 * TILE_BYTES)
#define GEMM_SMEM_BYTES (3 * GSTAGE_BYTES)

#define CP_ASYNC16(dst, src) \
    asm volatile("cp.async.cg.shared.global [%0], [%1], 16;" :: "r"(dst), "l"(src))

#define CP_ASYNC16Z(dst, src, sz) \
    asm volatile("cp.async.ca.shared.global [%0], [%1], 16, %2;" \
                 :: "r"(dst), "l"(src), "r"(sz))

#define LDSM_X4(d0, d1, d2, d3, addr) \
    asm volatile("ldmatrix.sync.aligned.m8n8.x4.shared.b16 {%0,%1,%2,%3}, [%4];" \
                 : "=r"(d0), "=r"(d1), "=r"(d2), "=r"(d3) : "r"(addr))

#define LDSM_X4T(d0, d1, d2, d3, addr) \
    asm volatile("ldmatrix.sync.aligned.m8n8.x4.trans.shared.b16 {%0,%1,%2,%3}, [%4];" \
                 : "=r"(d0), "=r"(d1), "=r"(d2), "=r"(d3) : "r"(addr))

#define MMA16816(acc, a0, a1, a2, a3, b0, b1) \
    asm volatile( \
        "mma.sync.aligned.m16n8k16.row.col.f32.f16.f16.f32 " \
        "{%0,%1,%2,%3}, {%4,%5,%6,%7}, {%8,%9}, {%0,%1,%2,%3};" \
        : "+f"((acc)[0]), "+f"((acc)[1]), "+f"((acc)[2]), "+f"((acc)[3]) \
        : "r"(a0), "r"(a1), "r"(a2), "r"(a3), "r"(b0), "r"(b1))

__global__ __launch_bounds__(256, 2) void gemm_f16_kernel(
    const __half* __restrict__ A, const __half* __restrict__ B, float* __restrict__ C,
    int N, int K,
    const float* __restrict__ bias_a, const float* __restrict__ bias_b, int mode,
    __half* __restrict__ Qd, __half* __restrict__ Kd, __half* __restrict__ Vd)
{
    extern __shared__ char smc[];
    uint32_t smb;
    asm("{ .reg .u64 t; cvta.to.shared.u64 t, %1; cvt.u32.u64 %0, t; }"
        : "=r"(smb) : "l"(smc));

    const int tid = threadIdx.x;
    const int lane = tid & 31, warp = tid >> 5;
    const int wm = warp >> 2;
    const int wn = warp & 3;
    const int bn = blockIdx.x, bm = blockIdx.y;

    const int lrow = tid & 127;
    const int lhalf = tid >> 7;
    const uint32_t lxor = (uint32_t)((lrow & 7) << 4);

    const __half* Ag0 = A + (size_t)(bm * 128 + lrow) * K + lhalf * 32;
    const __half* Bg0 = B + (size_t)(bn * 128 + lrow) * K + lhalf * 32;
    uint32_t sdst[4];
    #pragma unroll
    for (int c = 0; c < 4; c++)
        sdst[c] = (uint32_t)(lrow * 128) + (((uint32_t)(lhalf * 64 + c * 16)) ^ lxor);

#define GF_ISSUE(T) do {                                                     \
        uint32_t _sb = smb + ((T) % 3) * GSTAGE_BYTES;                       \
        const __half* _ag = Ag0 + (T) * GBK;                                 \
        const __half* _bg = Bg0 + (T) * GBK;                                 \
        _Pragma("unroll")                                                    \
        for (int _c = 0; _c < 4; _c++) {                                     \
            CP_ASYNC16(_sb + sdst[_c], _ag + _c * 8);                        \
            CP_ASYNC16(_sb + TILE_BYTES + sdst[_c], _bg + _c * 8);           \
        }                                                                    \
        asm volatile("cp.async.commit_group;");                              \
    } while (0)

#define GF_ISSUE_H0(T) do {                                                  \
        uint32_t _sb = smb + ((T) % 3) * GSTAGE_BYTES;                       \
        const __half* _ag = Ag0 + (T) * GBK;                                 \
        const __half* _bg = Bg0 + (T) * GBK;                                 \
        _Pragma("unroll")                                                    \
        for (int _c = 0; _c < 2; _c++) {                                     \
            CP_ASYNC16(_sb + sdst[_c], _ag + _c * 8);                        \
            CP_ASYNC16(_sb + TILE_BYTES + sdst[_c], _bg + _c * 8);           \
        }                                                                    \
    } while (0)
#define GF_ISSUE_H1(T) do {                                                  \
        uint32_t _sb = smb + ((T) % 3) * GSTAGE_BYTES;                       \
        const __half* _ag = Ag0 + (T) * GBK;                                 \
        const __half* _bg = Bg0 + (T) * GBK;                                 \
        _Pragma("unroll")                                                    \
        for (int _c = 2; _c < 4; _c++) {                                     \
            CP_ASYNC16(_sb + sdst[_c], _ag + _c * 8);                        \
            CP_ASYNC16(_sb + TILE_BYTES + sdst[_c], _bg + _c * 8);           \
        }                                                                    \
        asm volatile("cp.async.commit_group;");                              \
    } while (0)

    float acc[4][4][4];
    #pragma unroll
    for (int i = 0; i < 4; i++)
        #pragma unroll
        for (int j = 0; j < 4; j++)
            #pragma unroll
            for (int q = 0; q < 4; q++) acc[i][j][q] = 0.f;

    GF_ISSUE(0);
    GF_ISSUE(1);

    const uint32_t a_off16 = (uint32_t)((lane >> 4) * 16);
    const uint32_t a_xor = (uint32_t)((lane & 7) << 4);
    const uint32_t a_base = (uint32_t)((wm * 64 + ((lane >> 3) & 1) * 8 + (lane & 7)) * 128);

    const uint32_t b_off16 = (uint32_t)(((lane >> 3) & 1) * 16);
    const uint32_t b_base = (uint32_t)(TILE_BYTES
        + (wn * 32 + (lane >> 4) * 8 + (lane & 7)) * 128);

    const int nk = K / GBK;
    for (int t = 0; t < nk; t++) {
        if (t < nk - 1) asm volatile("cp.async.wait_group 1;");
        else            asm volatile("cp.async.wait_group 0;");
        __syncthreads();

        const bool pre = (t + 2 < nk);
        if (pre) GF_ISSUE_H0(t + 2);

        const uint32_t stg = smb + (t % 3) * GSTAGE_BYTES;

        #pragma unroll
        for (int ks = 0; ks < 4; ks++) {
            if (ks == 2 && pre) GF_ISSUE_H1(t + 2);

            const uint32_t aoff = ((uint32_t)(ks * 32) + a_off16) ^ a_xor;
            const uint32_t boff = ((uint32_t)(ks * 32) + b_off16) ^ a_xor;

            uint32_t af[4][4], bf[4][2];
            #pragma unroll
            for (int i = 0; i < 4; i++)
                LDSM_X4(af[i][0], af[i][1], af[i][2], af[i][3],
                        stg + a_base + i * 2048 + aoff);
            LDSM_X4(bf[0][0], bf[0][1], bf[1][0], bf[1][1],
                    stg + b_base + boff);
            LDSM_X4(bf[2][0], bf[2][1], bf[3][0], bf[3][1],
                    stg + b_base + 2048 + boff);

            #pragma unroll
            for (int i = 0; i < 4; i++)
                #pragma unroll
                for (int j = 0; j < 4; j++)
                    MMA16816(acc[i][j], af[i][0], af[i][1], af[i][2], af[i][3],
                             bf[j][0], bf[j][1]);
        }
    }

    const int g = lane >> 2;
    const int c2 = (lane & 3) * 2;
    if (mode == 1) {
        float bj0[4], bj1[4], sclj[4];
        __half* dstj[4];
        int dj[4];
        #pragma unroll
        for (int j = 0; j < 4; j++) {
            int gn = bn * 128 + wn * 32 + j * 8 + c2;
            bj0[j] = (gn < 768) ? bias_a[gn] : ((gn < 1536) ? 0.f : bias_b[gn - 1536]);
            int g1 = gn + 1;
            bj1[j] = (g1 < 768) ? bias_a[g1] : ((g1 < 1536) ? 0.f : bias_b[g1 - 1536]);
            int which = gn / 768;
            int rem = gn - which * 768;
            dstj[j] = (which == 0) ? Qd : ((which == 1) ? Kd : Vd);
            dj[j] = ((rem >> 6) * 197) * 64 + (rem & 63);
            sclj[j] = (which == 0) ? (0.125f * LOG2E) : 1.f;
        }
        #pragma unroll
        for (int i = 0; i < 4; i++) {
            int gm0 = bm * 128 + wm * 64 + i * 16 + g;
            int b0i = gm0 / 197, t0i = gm0 - b0i * 197;
            int gm1 = gm0 + 8;
            int b1i = gm1 / 197, t1i = gm1 - b1i * 197;
            size_t r0 = ((size_t)(b0i * 12) * 197 + t0i) * 64;
            size_t r1 = ((size_t)(b1i * 12) * 197 + t1i) * 64;
            #pragma unroll
            for (int j = 0; j < 4; j++) {
                __half2 h0 = __floats2half2_rn((acc[i][j][0] + bj0[j]) * sclj[j],
                                               (acc[i][j][1] + bj1[j]) * sclj[j]);
                __half2 h1 = __floats2half2_rn((acc[i][j][2] + bj0[j]) * sclj[j],
                                               (acc[i][j][3] + bj1[j]) * sclj[j]);
                *(__half2*)(dstj[j] + r0 + dj[j]) = h0;
                *(__half2*)(dstj[j] + r1 + dj[j]) = h1;
            }
        }
    } else {
        #pragma unroll
        for (int j = 0; j < 4; j++) {
            int gn = bn * 128 + wn * 32 + j * 8 + c2;
            float bv0 = bias_a[gn], bv1 = bias_a[gn + 1];
            #pragma unroll
            for (int i = 0; i < 4; i++) {
                size_t gm0 = (size_t)bm * 128 + wm * 64 + i * 16 + g;
                *(float2*)(C + gm0 * N + gn) =
                    make_float2(acc[i][j][0] + bv0, acc[i][j][1] + bv1);
                *(float2*)(C + (gm0 + 8) * N + gn) =
                    make_float2(acc[i][j][2] + bv0, acc[i][j][3] + bv1);
            }
        }
    }
}

// ---------------------------------------------------------------------------
// Persistent flash-style fp16 attention: 296 CTAs loop over all 1536 (b,h)
// pairs (no wave-tail). Unstabilized base-2 softmax. Full blocks (<12) store
// unconditionally.
// ---------------------------------------------------------------------------
#define ATHREADS 256
#define AK_BYTES (NT2 * 128)
#define QS_OFF   (2 * AK_BYTES)
#define ATTN_SMEM_BYTES (3 * AK_BYTES)

__global__ __launch_bounds__(ATHREADS, 2) void attn_f16_kernel(
    const __half* __restrict__ q, const __half* __restrict__ k,
    const __half* __restrict__ v, const uint2* __restrict__ biasF2,
    __half* __restrict__ out)
{
    extern __shared__ char smc[];
    uint32_t smb;
    asm("{ .reg .u64 t; cvta.to.shared.u64 t, %1; cvt.u32.u64 %0, t; }"
        : "=r"(smb) : "l"(smc));

    const int tid = threadIdx.x;
    const int lane = tid & 31, warp = tid >> 5;
    const int g = lane >> 2, c = lane & 3;

    const uint32_t swz = (uint32_t)(lane & 7) << 4;
    const int a_rowoff = ((lane >> 3) & 1) * 8 + (lane & 7);
    const uint32_t a_off16 = (uint32_t)((lane >> 4) << 4);
    const int k_rowoff = ((lane >> 4) << 3) + (lane & 7);
    const uint32_t k_off16 = (uint32_t)(((lane >> 3) & 1) << 4);
    const int v_rowoff = (lane & 7) + (((lane >> 3) & 1) << 3);
    const uint32_t v_off16 = (uint32_t)((lane >> 4) << 4);

    for (int bh = blockIdx.x; bh < NBH; bh += APERS) {
        const int b = bh / NHEAD;
        const int h = bh - b * NHEAD;

        const size_t hb = (size_t)bh * NTOK * HD;
        const __half* Qh = q + hb;
        const __half* Kh = k + hb;
        const __half* Vh = v + hb;

        // stage K, V, Q (swizzled 128B rows); pad rows zero-filled
        for (int i = tid; i < NT2 * 8; i += ATHREADS) {
            int row = i >> 3, cb = (i & 7) * 16;
            int rc = (row < NTOK) ? row : 0;
            int sz = (row < NTOK) ? 16 : 0;
            uint32_t off = smb + (uint32_t)(row * 128)
                         + ((uint32_t)cb ^ ((uint32_t)(row & 7) << 4));
            const char* kp = (const char*)(Kh + rc * 64) + cb;
            const char* vp = (const char*)(Vh + rc * 64) + cb;
            const char* qp = (const char*)(Qh + rc * 64) + cb;
            CP_ASYNC16Z(off, kp, sz);
            CP_ASYNC16Z(off + AK_BYTES, vp, sz);
            CP_ASYNC16Z(off + 2 * AK_BYTES, qp, sz);
        }
        asm volatile("cp.async.commit_group;");
        asm volatile("cp.async.wait_group 0;");
        __syncthreads();

        for (int blk = warp; blk < 13; blk += 8) {
            const int i0 = blk * 16;

            uint32_t af[4][4];
            {
                const uint32_t qrowbase = smb + QS_OFF + (uint32_t)((i0 + a_rowoff) * 128);
                #pragma unroll
                for (int ks = 0; ks < 4; ks++)
                    LDSM_X4(af[ks][0], af[ks][1], af[ks][2], af[ks][3],
                            qrowbase + (((uint32_t)(ks * 32) + a_off16) ^ swz));
            }

            float oacc[8][4];
            #pragma unroll
            for (int nt = 0; nt < 8; nt++)
                oacc[nt][0] = oacc[nt][1] = oacc[nt][2] = oacc[nt][3] = 0.f;
            float llo = 0.f, lhi = 0.f;

            const uint2* bfb = biasF2 + (((size_t)h * 13 + blk) * 26) * 32 + lane;

            #pragma unroll
            for (int ch = 0; ch < 2; ch++) {
                const int npairs = (ch == 0) ? 7 : 6;
                const int cbase = (ch == 0) ? 0 : 112;
                const int jtbase = (ch == 0) ? 0 : 14;
                const int ntiles = 2 * npairs;

                float sacc[14][4];
                for (int jt = 0; jt < ntiles; jt++) {
                    uint2 u = bfb[(jtbase + jt) * 32];
                    float2 blo = __half22float2(*(__half2*)&u.x);
                    float2 bhi = __half22float2(*(__half2*)&u.y);
                    sacc[jt][0] = blo.x; sacc[jt][1] = blo.y;
                    sacc[jt][2] = bhi.x; sacc[jt][3] = bhi.y;
                }

                for (int jp = 0; jp < npairs; jp++) {
                    const uint32_t krowbase = smb
                        + (uint32_t)((cbase + jp * 16 + k_rowoff) * 128);
                    #pragma unroll
                    for (int ks = 0; ks < 4; ks++) {
                        uint32_t b0, b1, b2, b3;
                        LDSM_X4(b0, b1, b2, b3,
                                krowbase + (((uint32_t)(ks * 32) + k_off16) ^ swz));
                        MMA16816(sacc[jp * 2], af[ks][0], af[ks][1], af[ks][2], af[ks][3], b0, b1);
                        MMA16816(sacc[jp * 2 + 1], af[ks][0], af[ks][1], af[ks][2], af[ks][3], b2, b3);
                    }
                }

                for (int jt = 0; jt < ntiles; jt++) {
                    sacc[jt][0] = fast_exp2(sacc[jt][0]); llo += sacc[jt][0];
                    sacc[jt][1] = fast_exp2(sacc[jt][1]); llo += sacc[jt][1];
                    sacc[jt][2] = fast_exp2(sacc[jt][2]); lhi += sacc[jt][2];
                    sacc[jt][3] = fast_exp2(sacc[jt][3]); lhi += sacc[jt][3];
                }

                for (int m = 0; m < npairs; m++) {
                    __half2 A0 = __floats2half2_rn(sacc[2 * m][0], sacc[2 * m][1]);
                    __half2 A1 = __floats2half2_rn(sacc[2 * m][2], sacc[2 * m][3]);
                    __half2 A2h = __floats2half2_rn(sacc[2 * m + 1][0], sacc[2 * m + 1][1]);
                    __half2 A3h = __floats2half2_rn(sacc[2 * m + 1][2], sacc[2 * m + 1][3]);
                    uint32_t a0 = *(uint32_t*)&A0, a1 = *(uint32_t*)&A1;
                    uint32_t a2 = *(uint32_t*)&A2h, a3 = *(uint32_t*)&A3h;

                    const uint32_t vrowbase = smb + AK_BYTES
                        + (uint32_t)((cbase + m * 16 + v_rowoff) * 128);
                    #pragma unroll
                    for (int dp = 0; dp < 4; dp++) {
                        uint32_t v0, v1, v2, v3;
                        LDSM_X4T(v0, v1, v2, v3,
                                 vrowbase + (((uint32_t)(dp * 32) + v_off16) ^ swz));
                        MMA16816(oacc[dp * 2],     a0, a1, a2, a3, v0, v1);
                        MMA16816(oacc[dp * 2 + 1], a0, a1, a2, a3, v2, v3);
                    }
                }
            }

            #pragma unroll
            for (int o = 1; o <= 2; o <<= 1) {
                llo += __shfl_xor_sync(0xffffffffu, llo, o);
                lhi += __shfl_xor_sync(0xffffffffu, lhi, o);
            }

            const float ilo = 1.f / llo, ihi = 1.f / lhi;
            const int gi0 = i0 + g, gi1 = i0 + g + 8;
            __half* ob0 = out + ((size_t)b * NTOK + gi0) * C_DIM + h * HD + 2 * c;
            __half* ob1 = out + ((size_t)b * NTOK + gi1) * C_DIM + h * HD + 2 * c;
            if (blk < 12) {
                // full block: rows always valid (gi1 <= 191)
                #pragma unroll
                for (int nt = 0; nt < 8; nt++) {
                    *(__half2*)(ob0 + nt * 8) = __floats2half2_rn(oacc[nt][0] * ilo, oacc[nt][1] * ilo);
                    *(__half2*)(ob1 + nt * 8) = __floats2half2_rn(oacc[nt][2] * ihi, oacc[nt][3] * ihi);
                }
            } else {
                #pragma unroll
                for (int nt = 0; nt < 8; nt++) {
                    if (gi0 < NTOK)
                        *(__half2*)(ob0 + nt * 8) = __floats2half2_rn(oacc[nt][0] * ilo, oacc[nt][1] * ilo);
                    if (gi1 < NTOK)
                        *(__half2*)(ob1 + nt * 8) = __floats2half2_rn(oacc[nt][2] * ihi, oacc[nt][3] * ihi);
                }
            }
        }
        __syncthreads();   // all warps done reading smem before next staging
    }
}

// ---------------------------------------------------------------------------
extern "C" void kernel_launch(void* const* d_in, const int* in_sizes, int n_in,
                              void* d_out, int out_size)
{
    const float* x      = (const float*)d_in[0];
    const float* qkv_w  = (const float*)d_in[1];
    const float* q_bias = (const float*)d_in[2];
    const float* v_bias = (const float*)d_in[3];
    const float* table  = (const float*)d_in[4];
    const float* proj_w = (const float*)d_in[5];
    const float* proj_b = (const float*)d_in[6];
    const int*   relIdx = (const int*)d_in[7];
    float* out = (float*)d_out;

    __half *qd, *kd, *vd, *attbuf, *xh, *wqkv, *wproj;
    uint2* bias2;
    cudaGetSymbolAddress((void**)&qd,     g_q);
    cudaGetSymbolAddress((void**)&kd,     g_k);
    cudaGetSymbolAddress((void**)&vd,     g_v);
    cudaGetSymbolAddress((void**)&attbuf, g_att);
    cudaGetSymbolAddress((void**)&xh,     g_xh);
    cudaGetSymbolAddress((void**)&wqkv,   g_wqkv);
    cudaGetSymbolAddress((void**)&wproj,  g_wproj);
    cudaGetSymbolAddress((void**)&bias2,  g_bias2);

    cudaFuncSetAttribute(gemm_f16_kernel, cudaFuncAttributeMaxDynamicSharedMemorySize,
                         GEMM_SMEM_BYTES);
    cudaFuncSetAttribute(attn_f16_kernel, cudaFuncAttributeMaxDynamicSharedMemorySize,
                         ATTN_SMEM_BYTES);

    // 0) fused prep: fp16 converts + fragment-layout bias (log2e domain)
    prep_kernel<<<CVT_BLOCKS + BIAS_BLOCKS, 256>>>(x, xh, qkv_w, wqkv, proj_w, wproj,
                                                   relIdx, table, bias2);

    // 1) QKV projection -> fp16 head-major q/k/v (q pre-scaled 0.125*log2e)
    dim3 g1(N3 / 128, M_TOT / 128);
    gemm_f16_kernel<<<g1, 256, GEMM_SMEM_BYTES>>>(xh, wqkv, nullptr, N3, C_DIM,
                                                  q_bias, v_bias, 1, qd, kd, vd);

    // 2) persistent flash-style fp16 attention (296 CTAs, no wave tail)
    attn_f16_kernel<<<APERS, ATHREADS, ATTN_SMEM_BYTES>>>(qd, kd, vd, bias2, attbuf);

    // 3) Output projection -> f32 out
    dim3 g2(C_DIM / 128, M_TOT / 128);
    gemm_f16_kernel<<<g2, 256, GEMM_SMEM_BYTES>>>(attbuf, wproj, out, C_DIM, C_DIM,
                                                  proj_b, nullptr, 0, nullptr, nullptr, nullptr);
}